// round 14
// baseline (speedup 1.0000x reference)
#include <cuda_runtime.h>
#include <cstdint>

// Static config (Fp8Padding num_gemms=8, align=16)
// M_SPLITS       = {4091, 8177, 2045, 4093, 6133, 1021, 4085, 8189}
// PADDED_SPLITS  = {4096, 8192, 2048, 4096, 6144, 1024, 4096, 8192}
// HIDDEN = 2048 floats = 256 x 32-byte chunks per row
//
// FINAL (converged, 13 rounds): DRAM-turnaround-bound streaming gather at
// ~6.45-6.55 TB/s (~81-82% of 8 TB/s spec; ~90% of the 77.5us
// irreducible-traffic floor: 310MB read + 310MB write, output poisoned so
// every byte must be written). Throughput verified invariant across
// VPT {1,2,4,8}, TPB {256,512}, 128/256-bit accesses, cache hints,
// occ 39-84%, and the copy-engine path (25% slower). SM-side never binding
// (issue 12%); LTS cap not binding (~11 TB/s at NAT clock).
// 256-bit global ld/st (sm_103a), 32-byte work units, 28 regs.
// TOTAL_OUT32 = 37888*256 = 9,699,328 = 9472 * 1024 exactly.

#define HIDDEN32    256                      // 32B chunks per row
#define TOTAL_OUT32 (37888 * HIDDEN32)       // 9,699,328
#define VPT         2                        // 32B chunks per thread
#define TPB         512
#define CHUNK       (TPB * VPT)              // 1024 chunks per block

__constant__ int c_out_start[8] = {0, 4096, 12288, 14336, 18432, 24576, 25600, 29696};
__constant__ int c_in_start [8] = {0, 4091, 12268, 14313, 18406, 24539, 25560, 29645};
__constant__ int c_m        [8] = {4091, 8177, 2045, 4093, 6133, 1021, 4085, 8189};

struct __align__(32) f32x8 { float x[8]; };

// Non-volatile pure load: lets ptxas reorder/front-batch the LDG.E.256s.
__device__ __forceinline__ void ldg256_cs(f32x8& v, const float* p) {
    asm("ld.global.cs.v8.f32 {%0,%1,%2,%3,%4,%5,%6,%7}, [%8];"
        : "=f"(v.x[0]), "=f"(v.x[1]), "=f"(v.x[2]), "=f"(v.x[3]),
          "=f"(v.x[4]), "=f"(v.x[5]), "=f"(v.x[6]), "=f"(v.x[7])
        : "l"(p));
}

__device__ __forceinline__ void stg256_cs(float* p, const f32x8& v) {
    asm volatile("st.global.cs.v8.f32 [%0], {%1,%2,%3,%4,%5,%6,%7,%8};"
        :: "l"(p),
           "f"(v.x[0]), "f"(v.x[1]), "f"(v.x[2]), "f"(v.x[3]),
           "f"(v.x[4]), "f"(v.x[5]), "f"(v.x[6]), "f"(v.x[7])
        : "memory");
}

__global__ void __launch_bounds__(TPB) fp8_padding_kernel(
    const float* __restrict__ in, float* __restrict__ out)
{
    int base = blockIdx.x * CHUNK + threadIdx.x;   // 32B-chunk index

    int  src_off[VPT];                             // float offsets (fit in int32)
    bool valid[VPT];
    #pragma unroll
    for (int k = 0; k < VPT; k++) {
        int idx = base + k * TPB;
        int row = idx >> 8;                        // 256 chunks per row
        int col = idx & (HIDDEN32 - 1);

        // Branch-free segment lookup over the 8 static padded-row boundaries.
        int seg = (row >= 4096)  + (row >= 12288) + (row >= 14336) + (row >= 18432)
                + (row >= 24576) + (row >= 25600) + (row >= 29696);

        int local = row - c_out_start[seg];
        valid[k]   = (local < c_m[seg]);
        src_off[k] = (c_in_start[seg] + local) * 2048 + col * 8;
    }

    f32x8 v[VPT];
    #pragma unroll
    for (int k = 0; k < VPT; k++) {
        if (valid[k]) {
            ldg256_cs(v[k], in + src_off[k]);      // front-batched LDG.E.256
        } else {
            #pragma unroll
            for (int j = 0; j < 8; j++) v[k].x[j] = 0.f;   // alignment pad row
        }
    }

    #pragma unroll
    for (int k = 0; k < VPT; k++) {
        stg256_cs(out + (long long)(base + k * TPB) * 8, v[k]);
    }
}

extern "C" void kernel_launch(void* const* d_in, const int* in_sizes, int n_in,
                              void* d_out, int out_size)
{
    const float* in  = (const float*)d_in[0];
    float*       out = (float*)d_out;
    // TOTAL_OUT32 = 9,699,328 = 9,472 * 1024 exactly
    fp8_padding_kernel<<<TOTAL_OUT32 / CHUNK, TPB>>>(in, out);
}

// round 15
// speedup vs baseline: 1.0007x; 1.0007x over previous
#include <cuda_runtime.h>
#include <cstdint>

// Static config (Fp8Padding num_gemms=8, align=16)
// M_SPLITS       = {4091, 8177, 2045, 4093, 6133, 1021, 4085, 8189}
// PADDED_SPLITS  = {4096, 8192, 2048, 4096, 6144, 1024, 4096, 8192}
// HIDDEN = 2048 floats = 256 x 32-byte chunks per row
//
// FINAL (converged, 14 rounds): DRAM-turnaround-bound streaming gather at
// ~6.45-6.55 TB/s (~81-82% of 8 TB/s spec; ~90% of the 77.5us
// irreducible-traffic floor: 310MB read + 310MB write, output poisoned so
// every byte must be written). Throughput verified invariant across
// VPT {1,2,4,8}, TPB {256,512}, 128/256-bit accesses, cache hints,
// occ 39-84%, and the copy-engine path (25% slower). SM-side never binding
// (issue 12%); LTS cap not binding (~11 TB/s at NAT clock).
// 256-bit global ld/st (sm_103a), 32-byte work units, 28 regs.
// TOTAL_OUT32 = 37888*256 = 9,699,328 = 9472 * 1024 exactly.

#define HIDDEN32    256                      // 32B chunks per row
#define TOTAL_OUT32 (37888 * HIDDEN32)       // 9,699,328
#define VPT         2                        // 32B chunks per thread
#define TPB         512
#define CHUNK       (TPB * VPT)              // 1024 chunks per block

__constant__ int c_out_start[8] = {0, 4096, 12288, 14336, 18432, 24576, 25600, 29696};
__constant__ int c_in_start [8] = {0, 4091, 12268, 14313, 18406, 24539, 25560, 29645};
__constant__ int c_m        [8] = {4091, 8177, 2045, 4093, 6133, 1021, 4085, 8189};

struct __align__(32) f32x8 { float x[8]; };

// Non-volatile pure load: lets ptxas reorder/front-batch the LDG.E.256s.
__device__ __forceinline__ void ldg256_cs(f32x8& v, const float* p) {
    asm("ld.global.cs.v8.f32 {%0,%1,%2,%3,%4,%5,%6,%7}, [%8];"
        : "=f"(v.x[0]), "=f"(v.x[1]), "=f"(v.x[2]), "=f"(v.x[3]),
          "=f"(v.x[4]), "=f"(v.x[5]), "=f"(v.x[6]), "=f"(v.x[7])
        : "l"(p));
}

__device__ __forceinline__ void stg256_cs(float* p, const f32x8& v) {
    asm volatile("st.global.cs.v8.f32 [%0], {%1,%2,%3,%4,%5,%6,%7,%8};"
        :: "l"(p),
           "f"(v.x[0]), "f"(v.x[1]), "f"(v.x[2]), "f"(v.x[3]),
           "f"(v.x[4]), "f"(v.x[5]), "f"(v.x[6]), "f"(v.x[7])
        : "memory");
}

__global__ void __launch_bounds__(TPB) fp8_padding_kernel(
    const float* __restrict__ in, float* __restrict__ out)
{
    int base = blockIdx.x * CHUNK + threadIdx.x;   // 32B-chunk index

    int  src_off[VPT];                             // float offsets (fit in int32)
    bool valid[VPT];
    #pragma unroll
    for (int k = 0; k < VPT; k++) {
        int idx = base + k * TPB;
        int row = idx >> 8;                        // 256 chunks per row
        int col = idx & (HIDDEN32 - 1);

        // Branch-free segment lookup over the 8 static padded-row boundaries.
        int seg = (row >= 4096)  + (row >= 12288) + (row >= 14336) + (row >= 18432)
                + (row >= 24576) + (row >= 25600) + (row >= 29696);

        int local = row - c_out_start[seg];
        valid[k]   = (local < c_m[seg]);
        src_off[k] = (c_in_start[seg] + local) * 2048 + col * 8;
    }

    f32x8 v[VPT];
    #pragma unroll
    for (int k = 0; k < VPT; k++) {
        if (valid[k]) {
            ldg256_cs(v[k], in + src_off[k]);      // front-batched LDG.E.256
        } else {
            #pragma unroll
            for (int j = 0; j < 8; j++) v[k].x[j] = 0.f;   // alignment pad row
        }
    }

    #pragma unroll
    for (int k = 0; k < VPT; k++) {
        stg256_cs(out + (long long)(base + k * TPB) * 8, v[k]);
    }
}

extern "C" void kernel_launch(void* const* d_in, const int* in_sizes, int n_in,
                              void* d_out, int out_size)
{
    const float* in  = (const float*)d_in[0];
    float*       out = (float*)d_out;
    // TOTAL_OUT32 = 9,699,328 = 9,472 * 1024 exactly
    fp8_padding_kernel<<<TOTAL_OUT32 / CHUNK, TPB>>>(in, out);
}

// round 16
// speedup vs baseline: 1.0031x; 1.0024x over previous
#include <cuda_runtime.h>
#include <cstdint>

// Static config (Fp8Padding num_gemms=8, align=16)
// M_SPLITS       = {4091, 8177, 2045, 4093, 6133, 1021, 4085, 8189}
// PADDED_SPLITS  = {4096, 8192, 2048, 4096, 6144, 1024, 4096, 8192}
// HIDDEN = 2048 floats = 256 x 32-byte chunks per row
//
// FINAL (converged, 15 rounds): DRAM-turnaround-bound streaming gather at
// ~6.45-6.55 TB/s (~81-82% of 8 TB/s spec; ~90% of the 77.5us
// irreducible-traffic floor: 310MB read + 310MB write, output poisoned so
// every byte must be written). Throughput verified invariant across
// VPT {1,2,4,8}, TPB {256,512}, 128/256-bit accesses, cache hints,
// occ 39-84%, and the copy-engine path (25% slower). SM-side never binding
// (issue 12%); LTS cap not binding (~11 TB/s at NAT clock).
// 256-bit global ld/st (sm_103a), 32-byte work units, 28 regs.
// TOTAL_OUT32 = 37888*256 = 9,699,328 = 9472 * 1024 exactly.

#define HIDDEN32    256                      // 32B chunks per row
#define TOTAL_OUT32 (37888 * HIDDEN32)       // 9,699,328
#define VPT         2                        // 32B chunks per thread
#define TPB         512
#define CHUNK       (TPB * VPT)              // 1024 chunks per block

__constant__ int c_out_start[8] = {0, 4096, 12288, 14336, 18432, 24576, 25600, 29696};
__constant__ int c_in_start [8] = {0, 4091, 12268, 14313, 18406, 24539, 25560, 29645};
__constant__ int c_m        [8] = {4091, 8177, 2045, 4093, 6133, 1021, 4085, 8189};

struct __align__(32) f32x8 { float x[8]; };

// Non-volatile pure load: lets ptxas reorder/front-batch the LDG.E.256s.
__device__ __forceinline__ void ldg256_cs(f32x8& v, const float* p) {
    asm("ld.global.cs.v8.f32 {%0,%1,%2,%3,%4,%5,%6,%7}, [%8];"
        : "=f"(v.x[0]), "=f"(v.x[1]), "=f"(v.x[2]), "=f"(v.x[3]),
          "=f"(v.x[4]), "=f"(v.x[5]), "=f"(v.x[6]), "=f"(v.x[7])
        : "l"(p));
}

__device__ __forceinline__ void stg256_cs(float* p, const f32x8& v) {
    asm volatile("st.global.cs.v8.f32 [%0], {%1,%2,%3,%4,%5,%6,%7,%8};"
        :: "l"(p),
           "f"(v.x[0]), "f"(v.x[1]), "f"(v.x[2]), "f"(v.x[3]),
           "f"(v.x[4]), "f"(v.x[5]), "f"(v.x[6]), "f"(v.x[7])
        : "memory");
}

__global__ void __launch_bounds__(TPB) fp8_padding_kernel(
    const float* __restrict__ in, float* __restrict__ out)
{
    int base = blockIdx.x * CHUNK + threadIdx.x;   // 32B-chunk index

    int  src_off[VPT];                             // float offsets (fit in int32)
    bool valid[VPT];
    #pragma unroll
    for (int k = 0; k < VPT; k++) {
        int idx = base + k * TPB;
        int row = idx >> 8;                        // 256 chunks per row
        int col = idx & (HIDDEN32 - 1);

        // Branch-free segment lookup over the 8 static padded-row boundaries.
        int seg = (row >= 4096)  + (row >= 12288) + (row >= 14336) + (row >= 18432)
                + (row >= 24576) + (row >= 25600) + (row >= 29696);

        int local = row - c_out_start[seg];
        valid[k]   = (local < c_m[seg]);
        src_off[k] = (c_in_start[seg] + local) * 2048 + col * 8;
    }

    f32x8 v[VPT];
    #pragma unroll
    for (int k = 0; k < VPT; k++) {
        if (valid[k]) {
            ldg256_cs(v[k], in + src_off[k]);      // front-batched LDG.E.256
        } else {
            #pragma unroll
            for (int j = 0; j < 8; j++) v[k].x[j] = 0.f;   // alignment pad row
        }
    }

    #pragma unroll
    for (int k = 0; k < VPT; k++) {
        stg256_cs(out + (long long)(base + k * TPB) * 8, v[k]);
    }
}

extern "C" void kernel_launch(void* const* d_in, const int* in_sizes, int n_in,
                              void* d_out, int out_size)
{
    const float* in  = (const float*)d_in[0];
    float*       out = (float*)d_out;
    // TOTAL_OUT32 = 9,699,328 = 9,472 * 1024 exactly
    fp8_padding_kernel<<<TOTAL_OUT32 / CHUNK, TPB>>>(in, out);
}

// round 17
// speedup vs baseline: 1.0034x; 1.0003x over previous
#include <cuda_runtime.h>
#include <cstdint>

// Static config (Fp8Padding num_gemms=8, align=16)
// M_SPLITS       = {4091, 8177, 2045, 4093, 6133, 1021, 4085, 8189}
// PADDED_SPLITS  = {4096, 8192, 2048, 4096, 6144, 1024, 4096, 8192}
// HIDDEN = 2048 floats = 256 x 32-byte chunks per row
//
// FINAL (converged, 16 rounds): DRAM-turnaround-bound streaming gather at
// ~6.45-6.55 TB/s (~81-82% of 8 TB/s spec; ~90% of the 77.5us
// irreducible-traffic floor: 310MB read + 310MB write, output poisoned so
// every byte must be written). Throughput verified invariant across
// VPT {1,2,4,8}, TPB {256,512}, 128/256-bit accesses, cache hints,
// occ 39-84%, and the copy-engine path (25% slower). SM-side never binding
// (issue 12%); LTS cap not binding (~11 TB/s at NAT clock).
// 256-bit global ld/st (sm_103a), 32-byte work units, 28 regs.
// TOTAL_OUT32 = 37888*256 = 9,699,328 = 9472 * 1024 exactly.

#define HIDDEN32    256                      // 32B chunks per row
#define TOTAL_OUT32 (37888 * HIDDEN32)       // 9,699,328
#define VPT         2                        // 32B chunks per thread
#define TPB         512
#define CHUNK       (TPB * VPT)              // 1024 chunks per block

__constant__ int c_out_start[8] = {0, 4096, 12288, 14336, 18432, 24576, 25600, 29696};
__constant__ int c_in_start [8] = {0, 4091, 12268, 14313, 18406, 24539, 25560, 29645};
__constant__ int c_m        [8] = {4091, 8177, 2045, 4093, 6133, 1021, 4085, 8189};

struct __align__(32) f32x8 { float x[8]; };

// Non-volatile pure load: lets ptxas reorder/front-batch the LDG.E.256s.
__device__ __forceinline__ void ldg256_cs(f32x8& v, const float* p) {
    asm("ld.global.cs.v8.f32 {%0,%1,%2,%3,%4,%5,%6,%7}, [%8];"
        : "=f"(v.x[0]), "=f"(v.x[1]), "=f"(v.x[2]), "=f"(v.x[3]),
          "=f"(v.x[4]), "=f"(v.x[5]), "=f"(v.x[6]), "=f"(v.x[7])
        : "l"(p));
}

__device__ __forceinline__ void stg256_cs(float* p, const f32x8& v) {
    asm volatile("st.global.cs.v8.f32 [%0], {%1,%2,%3,%4,%5,%6,%7,%8};"
        :: "l"(p),
           "f"(v.x[0]), "f"(v.x[1]), "f"(v.x[2]), "f"(v.x[3]),
           "f"(v.x[4]), "f"(v.x[5]), "f"(v.x[6]), "f"(v.x[7])
        : "memory");
}

__global__ void __launch_bounds__(TPB) fp8_padding_kernel(
    const float* __restrict__ in, float* __restrict__ out)
{
    int base = blockIdx.x * CHUNK + threadIdx.x;   // 32B-chunk index

    int  src_off[VPT];                             // float offsets (fit in int32)
    bool valid[VPT];
    #pragma unroll
    for (int k = 0; k < VPT; k++) {
        int idx = base + k * TPB;
        int row = idx >> 8;                        // 256 chunks per row
        int col = idx & (HIDDEN32 - 1);

        // Branch-free segment lookup over the 8 static padded-row boundaries.
        int seg = (row >= 4096)  + (row >= 12288) + (row >= 14336) + (row >= 18432)
                + (row >= 24576) + (row >= 25600) + (row >= 29696);

        int local = row - c_out_start[seg];
        valid[k]   = (local < c_m[seg]);
        src_off[k] = (c_in_start[seg] + local) * 2048 + col * 8;
    }

    f32x8 v[VPT];
    #pragma unroll
    for (int k = 0; k < VPT; k++) {
        if (valid[k]) {
            ldg256_cs(v[k], in + src_off[k]);      // front-batched LDG.E.256
        } else {
            #pragma unroll
            for (int j = 0; j < 8; j++) v[k].x[j] = 0.f;   // alignment pad row
        }
    }

    #pragma unroll
    for (int k = 0; k < VPT; k++) {
        stg256_cs(out + (long long)(base + k * TPB) * 8, v[k]);
    }
}

extern "C" void kernel_launch(void* const* d_in, const int* in_sizes, int n_in,
                              void* d_out, int out_size)
{
    const float* in  = (const float*)d_in[0];
    float*       out = (float*)d_out;
    // TOTAL_OUT32 = 9,699,328 = 9,472 * 1024 exactly
    fp8_padding_kernel<<<TOTAL_OUT32 / CHUNK, TPB>>>(in, out);
}